// round 4
// baseline (speedup 1.0000x reference)
#include <cuda_runtime.h>
#include <cuda_bf16.h>
#include <cstdint>

#define NN 50000
#define NE 800000
#define NG 64
#define NF 11
#define EF 14
#define HH 128
#define PP 128
#define NL 3
#define BN_EPS 1e-5f

#define NBLK 196   // ceil(NN/256)

// ---------------- scratch (__device__ globals; device-code references only) --
__device__ float g_h[NN * HH];
__device__ float g_z[NN * HH];
__device__ float g_t[NN * HH];
__device__ float g_eacsr[(size_t)NE * EF];
__device__ int   g_cnt[NN];
__device__ int   g_row[NN + 1];
__device__ int   g_cur[NN];
__device__ int   g_src[NE];
__device__ int   g_bsum[NBLK];
__device__ int   g_boff[NBLK];
__device__ float g_scale[NL * HH];
__device__ float g_shift[NL * HH];
__device__ float g_pool[NG * HH];
__device__ float g_gcnt[NG];

// ---------------- zero scratch + fold BN ------------------------------------
__global__ void __launch_bounds__(256) init_kernel(const float* __restrict__ lin1_b,
                                                   const float* __restrict__ gamma,
                                                   const float* __restrict__ beta,
                                                   const float* __restrict__ mean,
                                                   const float* __restrict__ var) {
    int i = blockIdx.x * blockDim.x + threadIdx.x;
    if (i < NN) g_cnt[i] = 0;
    if (i < NG * HH) g_pool[i] = 0.f;
    if (i < NG) g_gcnt[i] = 0.f;
    if (i < NL * HH) {
        float sc = gamma[i] * rsqrtf(var[i] + BN_EPS);
        g_scale[i] = sc;
        g_shift[i] = (lin1_b[i] - mean[i]) * sc + beta[i];
    }
}

// ---------------- node embedding: h = x @ node_W^T + node_b -----------------
__global__ void __launch_bounds__(128) node_embed(const float* __restrict__ x,
                                                  const float* __restrict__ W,
                                                  const float* __restrict__ b) {
    __shared__ float xs[32 * NF];
    int t = threadIdx.x;
    float w[NF];
#pragma unroll
    for (int k = 0; k < NF; k++) w[k] = W[t * NF + k];
    float bias = b[t];
    int base = blockIdx.x * 32;
    for (int i = t; i < 32 * NF; i += 128) {
        int node = base + i / NF;
        xs[i] = (node < NN) ? x[node * NF + i % NF] : 0.f;
    }
    __syncthreads();
    for (int j = 0; j < 32; j++) {
        int node = base + j;
        if (node >= NN) break;
        float acc = bias;
#pragma unroll
        for (int k = 0; k < NF; k++) acc = fmaf(xs[j * NF + k], w[k], acc);
        g_h[node * HH + t] = acc;
    }
}

// ---------------- CSR build: hist + 3-phase parallel scan -------------------
__global__ void __launch_bounds__(256) hist_kernel(const int* __restrict__ ei) {
    int i = blockIdx.x * blockDim.x + threadIdx.x;
    if (i < NE) atomicAdd(&g_cnt[ei[NE + i]], 1);
}

// per-block sums
__global__ void __launch_bounds__(256) bsum_kernel() {
    __shared__ int ws[8];
    int t = threadIdx.x;
    int i = blockIdx.x * 256 + t;
    int v = (i < NN) ? g_cnt[i] : 0;
#pragma unroll
    for (int off = 16; off > 0; off >>= 1) v += __shfl_down_sync(0xffffffffu, v, off);
    if ((t & 31) == 0) ws[t >> 5] = v;
    __syncthreads();
    if (t < 8) {
        int s = ws[t];
#pragma unroll
        for (int off = 4; off > 0; off >>= 1) s += __shfl_down_sync(0xffu, s, off);
        if (t == 0) g_bsum[blockIdx.x] = s;
    }
}

// single-block exclusive scan of 196 block sums
__global__ void __launch_bounds__(256) bscan_kernel() {
    __shared__ int sm[256];
    int t = threadIdx.x;
    int v = (t < NBLK) ? g_bsum[t] : 0;
    sm[t] = v;
    __syncthreads();
    for (int off = 1; off < 256; off <<= 1) {
        int u = (t >= off) ? sm[t - off] : 0;
        __syncthreads();
        sm[t] += u;
        __syncthreads();
    }
    if (t < NBLK) g_boff[t] = sm[t] - v;    // exclusive
    if (t == 255) g_row[NN] = sm[255];      // total
}

// per-element offsets: block-local exclusive scan + block offset
__global__ void __launch_bounds__(256) bwrite_kernel() {
    __shared__ int ws[8];
    int t = threadIdx.x, lane = t & 31, w = t >> 5;
    int i = blockIdx.x * 256 + t;
    int v = (i < NN) ? g_cnt[i] : 0;
    int incl = v;
#pragma unroll
    for (int off = 1; off < 32; off <<= 1) {
        int u = __shfl_up_sync(0xffffffffu, incl, off);
        if (lane >= off) incl += u;
    }
    if (lane == 31) ws[w] = incl;
    __syncthreads();
    if (t < 8) {
        int s = ws[t];
        int is = s;
#pragma unroll
        for (int off = 1; off < 8; off <<= 1) {
            int u = __shfl_up_sync(0xffu, is, off);
            if (t >= off) is += u;
        }
        ws[t] = is - s;                     // exclusive warp offsets
    }
    __syncthreads();
    if (i < NN) {
        int excl = incl - v + ws[w] + g_boff[blockIdx.x];
        g_row[i] = excl;
        g_cur[i] = excl;
    }
}

// scatter: record src + permute edge_attr into CSR order
__global__ void __launch_bounds__(256) scatter_kernel(const int* __restrict__ ei,
                                                      const float* __restrict__ ea) {
    int i = blockIdx.x * blockDim.x + threadIdx.x;
    if (i < NE) {
        int d = ei[NE + i];
        int p = atomicAdd(&g_cur[d], 1);
        g_src[p] = ei[i];
        const float* s = ea + (size_t)i * EF;
        float* o = g_eacsr + (size_t)p * EF;
#pragma unroll
        for (int k = 0; k < EF; k++) o[k] = s[k];
    }
}

// ---------------- GINE aggregation: z = h + sum relu(h[src] + e_ij) ---------
// warp/node; lane owns 4 features; edge embedding recomputed; 2-edge unroll.
__global__ void __launch_bounds__(256) aggregate_kernel(const float* __restrict__ eW,
                                                        const float* __restrict__ eB) {
    int gid = blockIdx.x * blockDim.x + threadIdx.x;
    int node = gid >> 5;
    if (node >= NN) return;
    int lane = gid & 31;

    float w[4][EF];
    float eb[4];
#pragma unroll
    for (int c = 0; c < 4; c++) {
        eb[c] = eB[4 * lane + c];
#pragma unroll
        for (int k = 0; k < EF; k++) w[c][k] = eW[(4 * lane + c) * EF + k];
    }

    const float4* hp = (const float4*)g_h;
    float4 accA = make_float4(0.f, 0.f, 0.f, 0.f);
    float4 accB = make_float4(0.f, 0.f, 0.f, 0.f);
    int beg = g_row[node], end = g_row[node + 1];
    int i = beg;
    for (; i + 2 <= end; i += 2) {
        int s0 = __ldg(&g_src[i]);
        int s1 = __ldg(&g_src[i + 1]);
        float av0 = (lane < EF) ? __ldg(&g_eacsr[(size_t)i * EF + lane]) : 0.f;
        float av1 = (lane < EF) ? __ldg(&g_eacsr[(size_t)(i + 1) * EF + lane]) : 0.f;
        float4 h0 = hp[s0 * 32 + lane];
        float4 h1 = hp[s1 * 32 + lane];
        float a0 = eb[0], a1 = eb[1], a2 = eb[2], a3 = eb[3];
        float b0 = eb[0], b1 = eb[1], b2 = eb[2], b3 = eb[3];
#pragma unroll
        for (int k = 0; k < EF; k++) {
            float e0 = __shfl_sync(0xffffffffu, av0, k);
            float e1 = __shfl_sync(0xffffffffu, av1, k);
            a0 = fmaf(w[0][k], e0, a0); b0 = fmaf(w[0][k], e1, b0);
            a1 = fmaf(w[1][k], e0, a1); b1 = fmaf(w[1][k], e1, b1);
            a2 = fmaf(w[2][k], e0, a2); b2 = fmaf(w[2][k], e1, b2);
            a3 = fmaf(w[3][k], e0, a3); b3 = fmaf(w[3][k], e1, b3);
        }
        accA.x += fmaxf(h0.x + a0, 0.f);  accB.x += fmaxf(h1.x + b0, 0.f);
        accA.y += fmaxf(h0.y + a1, 0.f);  accB.y += fmaxf(h1.y + b1, 0.f);
        accA.z += fmaxf(h0.z + a2, 0.f);  accB.z += fmaxf(h1.z + b2, 0.f);
        accA.w += fmaxf(h0.w + a3, 0.f);  accB.w += fmaxf(h1.w + b3, 0.f);
    }
    if (i < end) {
        int s0 = __ldg(&g_src[i]);
        float av0 = (lane < EF) ? __ldg(&g_eacsr[(size_t)i * EF + lane]) : 0.f;
        float4 h0 = hp[s0 * 32 + lane];
        float a0 = eb[0], a1 = eb[1], a2 = eb[2], a3 = eb[3];
#pragma unroll
        for (int k = 0; k < EF; k++) {
            float e0 = __shfl_sync(0xffffffffu, av0, k);
            a0 = fmaf(w[0][k], e0, a0);
            a1 = fmaf(w[1][k], e0, a1);
            a2 = fmaf(w[2][k], e0, a2);
            a3 = fmaf(w[3][k], e0, a3);
        }
        accA.x += fmaxf(h0.x + a0, 0.f);
        accA.y += fmaxf(h0.y + a1, 0.f);
        accA.z += fmaxf(h0.z + a2, 0.f);
        accA.w += fmaxf(h0.w + a3, 0.f);
    }
    float4 hv = hp[node * 32 + lane];
    accA.x += accB.x + hv.x;
    accA.y += accB.y + hv.y;
    accA.z += accB.z + hv.z;
    accA.w += accB.w + hv.w;
    ((float4*)g_z)[node * 32 + lane] = accA;
}

// ---------------- SGEMM tiles: C[64 x 128], K=128, chunks of 32 -------------
// 256 threads, 4x8 micro-tile, 3 blocks/SM.
#define AL 68
#define WL 132

__device__ __forceinline__ void load_chunk64(const float* __restrict__ A,
                                             const float* __restrict__ W,
                                             float* As, float* Ws,
                                             int rowbase, int kc, int t) {
    const float4* A4 = (const float4*)A;
    const float4* W4 = (const float4*)W;
    int kq4 = kc >> 2;
    // A: 64 rows x 8 float4 = 512 float4 -> 2 per thread
#pragma unroll
    for (int r = 0; r < 2; r++) {
        int idx = t + 256 * r;
        int m = idx >> 3;           // 0..63
        int kq = idx & 7;
        int row = rowbase + m;
        float4 v = make_float4(0.f, 0.f, 0.f, 0.f);
        if (row < NN) v = A4[row * 32 + kq4 + kq];
        As[(kq * 4 + 0) * AL + m] = v.x;
        As[(kq * 4 + 1) * AL + m] = v.y;
        As[(kq * 4 + 2) * AL + m] = v.z;
        As[(kq * 4 + 3) * AL + m] = v.w;
    }
    // W: 128 rows x 8 float4 = 1024 float4 -> 4 per thread
#pragma unroll
    for (int r = 0; r < 4; r++) {
        int idx = t + 256 * r;
        int n = idx >> 3;           // 0..127
        int kq = idx & 7;
        float4 wv = W4[n * 32 + kq4 + kq];
        Ws[(kq * 4 + 0) * WL + n] = wv.x;
        Ws[(kq * 4 + 1) * WL + n] = wv.y;
        Ws[(kq * 4 + 2) * WL + n] = wv.z;
        Ws[(kq * 4 + 3) * WL + n] = wv.w;
    }
}

__device__ __forceinline__ void gemm_accum64(const float* As, const float* Ws,
                                             int m0, int n0, float acc[4][8]) {
#pragma unroll
    for (int k = 0; k < 32; k++) {
        float4 a0 = *(const float4*)&As[k * AL + m0];
        float4 b0 = *(const float4*)&Ws[k * WL + n0];
        float4 b1 = *(const float4*)&Ws[k * WL + n0 + 4];
        float a[4] = {a0.x, a0.y, a0.z, a0.w};
        float b[8] = {b0.x, b0.y, b0.z, b0.w, b1.x, b1.y, b1.z, b1.w};
#pragma unroll
        for (int j = 0; j < 4; j++)
#pragma unroll
            for (int i = 0; i < 8; i++) acc[j][i] = fmaf(a[j], b[i], acc[j][i]);
    }
}

// pass 1: g_t = relu(scale[li] * (g_z @ W1^T) + shift[li])
__global__ void __launch_bounds__(256, 3) gemm1_kernel(const float* __restrict__ W1,
                                                       int li) {
    __shared__ float As[32 * AL];
    __shared__ float Ws[32 * WL];
    int t = threadIdx.x;
    int m0 = (t >> 4) * 4;          // 0..60
    int n0 = (t & 15) * 8;          // 0..120
    int rowbase = blockIdx.x * 64;

    float acc[4][8];
#pragma unroll
    for (int j = 0; j < 4; j++)
#pragma unroll
        for (int i = 0; i < 8; i++) acc[j][i] = 0.f;

    for (int kc = 0; kc < 128; kc += 32) {
        load_chunk64(g_z, W1, As, Ws, rowbase, kc, t);
        __syncthreads();
        gemm_accum64(As, Ws, m0, n0, acc);
        __syncthreads();
    }

    float sc[8], sh[8];
#pragma unroll
    for (int i = 0; i < 8; i++) {
        sc[i] = g_scale[li * HH + n0 + i];
        sh[i] = g_shift[li * HH + n0 + i];
    }
#pragma unroll
    for (int j = 0; j < 4; j++) {
        int row = rowbase + m0 + j;
        if (row < NN) {
            float o[8];
#pragma unroll
            for (int i = 0; i < 8; i++) o[i] = fmaxf(fmaf(acc[j][i], sc[i], sh[i]), 0.f);
            *(float4*)&g_t[row * 128 + n0]     = make_float4(o[0], o[1], o[2], o[3]);
            *(float4*)&g_t[row * 128 + n0 + 4] = make_float4(o[4], o[5], o[6], o[7]);
        }
    }
}

// pass 2: g_h = relu(g_t @ W2^T + b2) + g_h
__global__ void __launch_bounds__(256, 3) gemm2_kernel(const float* __restrict__ W2,
                                                       const float* __restrict__ b2) {
    __shared__ float As[32 * AL];
    __shared__ float Ws[32 * WL];
    int t = threadIdx.x;
    int m0 = (t >> 4) * 4;
    int n0 = (t & 15) * 8;
    int rowbase = blockIdx.x * 64;

    float acc[4][8];
#pragma unroll
    for (int j = 0; j < 4; j++)
#pragma unroll
        for (int i = 0; i < 8; i++) acc[j][i] = 0.f;

    for (int kc = 0; kc < 128; kc += 32) {
        load_chunk64(g_t, W2, As, Ws, rowbase, kc, t);
        __syncthreads();
        gemm_accum64(As, Ws, m0, n0, acc);
        __syncthreads();
    }

    float bias[8];
#pragma unroll
    for (int i = 0; i < 8; i++) bias[i] = b2[n0 + i];
#pragma unroll
    for (int j = 0; j < 4; j++) {
        int row = rowbase + m0 + j;
        if (row < NN) {
            float4 h0 = *(const float4*)&g_h[row * 128 + n0];
            float4 h1 = *(const float4*)&g_h[row * 128 + n0 + 4];
            float4 o0, o1;
            o0.x = fmaxf(acc[j][0] + bias[0], 0.f) + h0.x;
            o0.y = fmaxf(acc[j][1] + bias[1], 0.f) + h0.y;
            o0.z = fmaxf(acc[j][2] + bias[2], 0.f) + h0.z;
            o0.w = fmaxf(acc[j][3] + bias[3], 0.f) + h0.w;
            o1.x = fmaxf(acc[j][4] + bias[4], 0.f) + h1.x;
            o1.y = fmaxf(acc[j][5] + bias[5], 0.f) + h1.y;
            o1.z = fmaxf(acc[j][6] + bias[6], 0.f) + h1.z;
            o1.w = fmaxf(acc[j][7] + bias[7], 0.f) + h1.w;
            *(float4*)&g_h[row * 128 + n0]     = o0;
            *(float4*)&g_h[row * 128 + n0 + 4] = o1;
        }
    }
}

// ---------------- pooling (batch_idx sorted -> run-length accumulation) -----
__global__ void __launch_bounds__(128) pool_kernel(const int* __restrict__ batch) {
    int t = threadIdx.x;
    int base = blockIdx.x * 128;
    float acc = 0.f, runc = 0.f;
    int cur = -1;
    for (int j = 0; j < 128; j++) {
        int node = base + j;
        if (node >= NN) break;
        int g = batch[node];
        if (g != cur) {
            if (cur >= 0) {
                atomicAdd(&g_pool[cur * 128 + t], acc);
                if (t == 0) atomicAdd(&g_gcnt[cur], runc);
            }
            cur = g; acc = 0.f; runc = 0.f;
        }
        acc += g_h[node * 128 + t];
        runc += 1.f;
    }
    if (cur >= 0) {
        atomicAdd(&g_pool[cur * 128 + t], acc);
        if (t == 0) atomicAdd(&g_gcnt[cur], runc);
    }
}

// ---------------- final projection ------------------------------------------
__global__ void __launch_bounds__(128) proj_kernel(const float* __restrict__ pW,
                                                   const float* __restrict__ pb,
                                                   float* __restrict__ out) {
    __shared__ float pr[128];
    int g = blockIdx.x, t = threadIdx.x;
    float c = fmaxf(g_gcnt[g], 1.f);
    pr[t] = g_pool[g * 128 + t] / c;
    __syncthreads();
    float acc = pb[t];
#pragma unroll 4
    for (int h = 0; h < 128; h++) acc = fmaf(pr[h], pW[t * 128 + h], acc);
    out[g * 128 + t] = acc;
}

// ---------------- launch ------------------------------------------------------
extern "C" void kernel_launch(void* const* d_in, const int* in_sizes, int n_in,
                              void* d_out, int out_size) {
    const float* x       = (const float*)d_in[0];
    const int*   ei      = (const int*)  d_in[1];
    const float* ea      = (const float*)d_in[2];
    const int*   batch   = (const int*)  d_in[3];
    const float* node_W  = (const float*)d_in[4];
    const float* node_b  = (const float*)d_in[5];
    const float* edge_W  = (const float*)d_in[6];
    const float* edge_b  = (const float*)d_in[7];
    const float* lin1_W  = (const float*)d_in[8];
    const float* lin1_b  = (const float*)d_in[9];
    const float* bn_g    = (const float*)d_in[10];
    const float* bn_b    = (const float*)d_in[11];
    const float* bn_m    = (const float*)d_in[12];
    const float* bn_v    = (const float*)d_in[13];
    const float* lin2_W  = (const float*)d_in[14];
    const float* lin2_b  = (const float*)d_in[15];
    const float* proj_W  = (const float*)d_in[16];
    const float* proj_b  = (const float*)d_in[17];
    float* out = (float*)d_out;

    init_kernel<<<NBLK, 256>>>(lin1_b, bn_g, bn_b, bn_m, bn_v);
    node_embed<<<(NN + 31) / 32, 128>>>(x, node_W, node_b);
    hist_kernel<<<(NE + 255) / 256, 256>>>(ei);
    bsum_kernel<<<NBLK, 256>>>();
    bscan_kernel<<<1, 256>>>();
    bwrite_kernel<<<NBLK, 256>>>();
    scatter_kernel<<<(NE + 255) / 256, 256>>>(ei, ea);

    const int gemm_grid = (NN + 63) / 64;
    for (int li = 0; li < NL; li++) {
        aggregate_kernel<<<(NN * 32 + 255) / 256, 256>>>(edge_W, edge_b);
        gemm1_kernel<<<gemm_grid, 256>>>(lin1_W + li * HH * HH, li);
        gemm2_kernel<<<gemm_grid, 256>>>(lin2_W + li * HH * HH, lin2_b + li * HH);
    }

    pool_kernel<<<(NN + 127) / 128, 128>>>(batch);
    proj_kernel<<<NG, 128>>>(proj_W, proj_b, out);
}

// round 5
// speedup vs baseline: 1.0230x; 1.0230x over previous
#include <cuda_runtime.h>
#include <cuda_bf16.h>
#include <cstdint>

#define NN 50000
#define NE 800000
#define NG 64
#define NF 11
#define EF 14
#define HH 128
#define PP 128
#define NL 3
#define BN_EPS 1e-5f

#define NE_BLOCKS 1563          // node-embed blocks (32 nodes each)
#define HIST_BLOCKS 1563        // hist blocks (512 edges each)
#define FUSED_GRID (NE_BLOCKS + HIST_BLOCKS + 3)

// ---------------- scratch (__device__ globals; device-code references only) --
// Invariant: g_cnt, g_pool, g_gcnt are ZERO on entry to kernel_launch
// (zero-initialized at load; re-zeroed by cleanup_kernel at end of every call).
__device__ float g_h[NN * HH];
__device__ float g_z[NN * HH];
__device__ float g_t[NN * HH];
__device__ float g_eacsr[(size_t)NE * EF];
__device__ int   g_cnt[NN];
__device__ int   g_row[NN + 1];
__device__ int   g_cur[NN];
__device__ int   g_src[NE];
__device__ float g_scale[NL * HH];
__device__ float g_shift[NL * HH];
__device__ float g_pool[NG * HH];
__device__ float g_gcnt[NG];

// ---------------- launch #1: node_embed + edge histogram + BN fold ----------
__global__ void __launch_bounds__(128) fused_front(const float* __restrict__ x,
                                                   const float* __restrict__ nW,
                                                   const float* __restrict__ nb,
                                                   const int* __restrict__ ei,
                                                   const float* __restrict__ lin1_b,
                                                   const float* __restrict__ gamma,
                                                   const float* __restrict__ beta,
                                                   const float* __restrict__ mean,
                                                   const float* __restrict__ var) {
    int b = blockIdx.x;
    int t = threadIdx.x;
    if (b < NE_BLOCKS) {
        // node embedding: h = x @ node_W^T + node_b, 32 nodes per block
        __shared__ float xs[32 * NF];
        float w[NF];
#pragma unroll
        for (int k = 0; k < NF; k++) w[k] = nW[t * NF + k];
        float bias = nb[t];
        int base = b * 32;
        for (int i = t; i < 32 * NF; i += 128) {
            int node = base + i / NF;
            xs[i] = (node < NN) ? x[node * NF + i % NF] : 0.f;
        }
        __syncthreads();
        for (int j = 0; j < 32; j++) {
            int node = base + j;
            if (node >= NN) break;
            float acc = bias;
#pragma unroll
            for (int k = 0; k < NF; k++) acc = fmaf(xs[j * NF + k], w[k], acc);
            g_h[node * HH + t] = acc;
        }
    } else if (b < NE_BLOCKS + HIST_BLOCKS) {
        int base = (b - NE_BLOCKS) * 512;
#pragma unroll
        for (int r = 0; r < 4; r++) {
            int i = base + r * 128 + t;
            if (i < NE) atomicAdd(&g_cnt[ei[NE + i]], 1);
        }
    } else {
        int i = (b - NE_BLOCKS - HIST_BLOCKS) * 128 + t;
        if (i < NL * HH) {
            float sc = gamma[i] * rsqrtf(var[i] + BN_EPS);
            g_scale[i] = sc;
            g_shift[i] = (lin1_b[i] - mean[i]) * sc + beta[i];
        }
    }
}

// ---------------- launch #2: single-block scan ------------------------------
__global__ void __launch_bounds__(1024) scan_kernel() {
    __shared__ int partial[1024];
    const int CH = (NN + 1023) / 1024;   // 49
    int t = threadIdx.x;
    int beg = t * CH;
    int sum = 0;
    for (int i = 0; i < CH; i++) {
        int idx = beg + i;
        if (idx < NN) sum += g_cnt[idx];
    }
    partial[t] = sum;
    __syncthreads();
    for (int off = 1; off < 1024; off <<= 1) {
        int v = (t >= off) ? partial[t - off] : 0;
        __syncthreads();
        partial[t] += v;
        __syncthreads();
    }
    int run = (t > 0) ? partial[t - 1] : 0;
    for (int i = 0; i < CH; i++) {
        int idx = beg + i;
        if (idx < NN) {
            g_row[idx] = run;
            g_cur[idx] = run;
            run += g_cnt[idx];
        }
    }
    if (t == 1023) g_row[NN] = run;
}

// ---------------- launch #3: scatter (src + edge_attr permute) --------------
__global__ void __launch_bounds__(256) scatter_kernel(const int* __restrict__ ei,
                                                      const float* __restrict__ ea) {
    int i = blockIdx.x * blockDim.x + threadIdx.x;
    if (i < NE) {
        int d = ei[NE + i];
        int p = atomicAdd(&g_cur[d], 1);
        g_src[p] = ei[i];
        const float* s = ea + (size_t)i * EF;
        float* o = g_eacsr + (size_t)p * EF;
#pragma unroll
        for (int k = 0; k < EF; k++) o[k] = s[k];
    }
}

// ---------------- launch #4 (PROFILED): GINE aggregation --------------------
// z = h + sum_j relu(h[src] + e_ij); warp/node; e recomputed via shfl.
__global__ void __launch_bounds__(256) aggregate_kernel(const float* __restrict__ eW,
                                                        const float* __restrict__ eB) {
    int gid = blockIdx.x * blockDim.x + threadIdx.x;
    int node = gid >> 5;
    if (node >= NN) return;
    int lane = gid & 31;

    float w[4][EF];
    float eb[4];
#pragma unroll
    for (int c = 0; c < 4; c++) {
        eb[c] = eB[4 * lane + c];
#pragma unroll
        for (int k = 0; k < EF; k++) w[c][k] = eW[(4 * lane + c) * EF + k];
    }

    const float4* hp = (const float4*)g_h;
    float4 accA = make_float4(0.f, 0.f, 0.f, 0.f);
    float4 accB = make_float4(0.f, 0.f, 0.f, 0.f);
    int beg = g_row[node], end = g_row[node + 1];
    int i = beg;
    for (; i + 2 <= end; i += 2) {
        int s0 = __ldg(&g_src[i]);
        int s1 = __ldg(&g_src[i + 1]);
        float av0 = (lane < EF) ? __ldg(&g_eacsr[(size_t)i * EF + lane]) : 0.f;
        float av1 = (lane < EF) ? __ldg(&g_eacsr[(size_t)(i + 1) * EF + lane]) : 0.f;
        float4 h0 = hp[s0 * 32 + lane];
        float4 h1 = hp[s1 * 32 + lane];
        float a0 = eb[0], a1 = eb[1], a2 = eb[2], a3 = eb[3];
        float b0 = eb[0], b1 = eb[1], b2 = eb[2], b3 = eb[3];
#pragma unroll
        for (int k = 0; k < EF; k++) {
            float e0 = __shfl_sync(0xffffffffu, av0, k);
            float e1 = __shfl_sync(0xffffffffu, av1, k);
            a0 = fmaf(w[0][k], e0, a0); b0 = fmaf(w[0][k], e1, b0);
            a1 = fmaf(w[1][k], e0, a1); b1 = fmaf(w[1][k], e1, b1);
            a2 = fmaf(w[2][k], e0, a2); b2 = fmaf(w[2][k], e1, b2);
            a3 = fmaf(w[3][k], e0, a3); b3 = fmaf(w[3][k], e1, b3);
        }
        accA.x += fmaxf(h0.x + a0, 0.f);  accB.x += fmaxf(h1.x + b0, 0.f);
        accA.y += fmaxf(h0.y + a1, 0.f);  accB.y += fmaxf(h1.y + b1, 0.f);
        accA.z += fmaxf(h0.z + a2, 0.f);  accB.z += fmaxf(h1.z + b2, 0.f);
        accA.w += fmaxf(h0.w + a3, 0.f);  accB.w += fmaxf(h1.w + b3, 0.f);
    }
    if (i < end) {
        int s0 = __ldg(&g_src[i]);
        float av0 = (lane < EF) ? __ldg(&g_eacsr[(size_t)i * EF + lane]) : 0.f;
        float4 h0 = hp[s0 * 32 + lane];
        float a0 = eb[0], a1 = eb[1], a2 = eb[2], a3 = eb[3];
#pragma unroll
        for (int k = 0; k < EF; k++) {
            float e0 = __shfl_sync(0xffffffffu, av0, k);
            a0 = fmaf(w[0][k], e0, a0);
            a1 = fmaf(w[1][k], e0, a1);
            a2 = fmaf(w[2][k], e0, a2);
            a3 = fmaf(w[3][k], e0, a3);
        }
        accA.x += fmaxf(h0.x + a0, 0.f);
        accA.y += fmaxf(h0.y + a1, 0.f);
        accA.z += fmaxf(h0.z + a2, 0.f);
        accA.w += fmaxf(h0.w + a3, 0.f);
    }
    float4 hv = hp[node * 32 + lane];
    accA.x += accB.x + hv.x;
    accA.y += accB.y + hv.y;
    accA.z += accB.z + hv.z;
    accA.w += accB.w + hv.w;
    ((float4*)g_z)[node * 32 + lane] = accA;
}

// ---------------- SGEMM (R3 config): C[128 x 128], K=128, chunks of 32 ------
#define AL 132
#define WL 132

__device__ __forceinline__ void load_chunk(const float* __restrict__ A,
                                           const float* __restrict__ W,
                                           float* As, float* Ws,
                                           int rowbase, int kc, int t) {
    const float4* A4 = (const float4*)A;
    const float4* W4 = (const float4*)W;
    int kq4 = kc >> 2;
#pragma unroll
    for (int r = 0; r < 4; r++) {
        int idx = t + 256 * r;
        int m = idx >> 3;
        int kq = idx & 7;
        int row = rowbase + m;
        float4 v = make_float4(0.f, 0.f, 0.f, 0.f);
        if (row < NN) v = A4[row * 32 + kq4 + kq];
        As[(kq * 4 + 0) * AL + m] = v.x;
        As[(kq * 4 + 1) * AL + m] = v.y;
        As[(kq * 4 + 2) * AL + m] = v.z;
        As[(kq * 4 + 3) * AL + m] = v.w;
        float4 wv = W4[m * 32 + kq4 + kq];
        Ws[(kq * 4 + 0) * WL + m] = wv.x;
        Ws[(kq * 4 + 1) * WL + m] = wv.y;
        Ws[(kq * 4 + 2) * WL + m] = wv.z;
        Ws[(kq * 4 + 3) * WL + m] = wv.w;
    }
}

__device__ __forceinline__ void gemm_accum(const float* As, const float* Ws,
                                           int m0, int n0, float acc[8][8]) {
#pragma unroll
    for (int k = 0; k < 32; k++) {
        float4 a0 = *(const float4*)&As[k * AL + m0];
        float4 a1 = *(const float4*)&As[k * AL + m0 + 4];
        float4 b0 = *(const float4*)&Ws[k * WL + n0];
        float4 b1 = *(const float4*)&Ws[k * WL + n0 + 4];
        float a[8] = {a0.x, a0.y, a0.z, a0.w, a1.x, a1.y, a1.z, a1.w};
        float b[8] = {b0.x, b0.y, b0.z, b0.w, b1.x, b1.y, b1.z, b1.w};
#pragma unroll
        for (int j = 0; j < 8; j++)
#pragma unroll
            for (int i = 0; i < 8; i++) acc[j][i] = fmaf(a[j], b[i], acc[j][i]);
    }
}

// pass 1: g_t = relu(scale[li] * (g_z @ W1^T) + shift[li])
__global__ void __launch_bounds__(256) gemm1_kernel(const float* __restrict__ W1,
                                                    int li) {
    __shared__ float As[32 * AL];
    __shared__ float Ws[32 * WL];
    int t = threadIdx.x;
    int m0 = (t >> 4) * 8;
    int n0 = (t & 15) * 8;
    int rowbase = blockIdx.x * 128;

    float acc[8][8];
#pragma unroll
    for (int j = 0; j < 8; j++)
#pragma unroll
        for (int i = 0; i < 8; i++) acc[j][i] = 0.f;

    for (int kc = 0; kc < 128; kc += 32) {
        load_chunk(g_z, W1, As, Ws, rowbase, kc, t);
        __syncthreads();
        gemm_accum(As, Ws, m0, n0, acc);
        __syncthreads();
    }

    float sc[8], sh[8];
#pragma unroll
    for (int i = 0; i < 8; i++) {
        sc[i] = g_scale[li * HH + n0 + i];
        sh[i] = g_shift[li * HH + n0 + i];
    }
#pragma unroll
    for (int j = 0; j < 8; j++) {
        int row = rowbase + m0 + j;
        if (row < NN) {
            float o[8];
#pragma unroll
            for (int i = 0; i < 8; i++) o[i] = fmaxf(fmaf(acc[j][i], sc[i], sh[i]), 0.f);
            *(float4*)&g_t[row * 128 + n0]     = make_float4(o[0], o[1], o[2], o[3]);
            *(float4*)&g_t[row * 128 + n0 + 4] = make_float4(o[4], o[5], o[6], o[7]);
        }
    }
}

// pass 2: g_h = relu(g_t @ W2^T + b2) + g_h
__global__ void __launch_bounds__(256) gemm2_kernel(const float* __restrict__ W2,
                                                    const float* __restrict__ b2) {
    __shared__ float As[32 * AL];
    __shared__ float Ws[32 * WL];
    int t = threadIdx.x;
    int m0 = (t >> 4) * 8;
    int n0 = (t & 15) * 8;
    int rowbase = blockIdx.x * 128;

    float acc[8][8];
#pragma unroll
    for (int j = 0; j < 8; j++)
#pragma unroll
        for (int i = 0; i < 8; i++) acc[j][i] = 0.f;

    for (int kc = 0; kc < 128; kc += 32) {
        load_chunk(g_t, W2, As, Ws, rowbase, kc, t);
        __syncthreads();
        gemm_accum(As, Ws, m0, n0, acc);
        __syncthreads();
    }

    float bias[8];
#pragma unroll
    for (int i = 0; i < 8; i++) bias[i] = b2[n0 + i];
#pragma unroll
    for (int j = 0; j < 8; j++) {
        int row = rowbase + m0 + j;
        if (row < NN) {
            float4 h0 = *(const float4*)&g_h[row * 128 + n0];
            float4 h1 = *(const float4*)&g_h[row * 128 + n0 + 4];
            float4 o0, o1;
            o0.x = fmaxf(acc[j][0] + bias[0], 0.f) + h0.x;
            o0.y = fmaxf(acc[j][1] + bias[1], 0.f) + h0.y;
            o0.z = fmaxf(acc[j][2] + bias[2], 0.f) + h0.z;
            o0.w = fmaxf(acc[j][3] + bias[3], 0.f) + h0.w;
            o1.x = fmaxf(acc[j][4] + bias[4], 0.f) + h1.x;
            o1.y = fmaxf(acc[j][5] + bias[5], 0.f) + h1.y;
            o1.z = fmaxf(acc[j][6] + bias[6], 0.f) + h1.z;
            o1.w = fmaxf(acc[j][7] + bias[7], 0.f) + h1.w;
            *(float4*)&g_h[row * 128 + n0]     = o0;
            *(float4*)&g_h[row * 128 + n0 + 4] = o1;
        }
    }
}

// ---------------- pooling ----------------------------------------------------
__global__ void __launch_bounds__(128) pool_kernel(const int* __restrict__ batch) {
    int t = threadIdx.x;
    int base = blockIdx.x * 128;
    float acc = 0.f, runc = 0.f;
    int cur = -1;
    for (int j = 0; j < 128; j++) {
        int node = base + j;
        if (node >= NN) break;
        int g = batch[node];
        if (g != cur) {
            if (cur >= 0) {
                atomicAdd(&g_pool[cur * 128 + t], acc);
                if (t == 0) atomicAdd(&g_gcnt[cur], runc);
            }
            cur = g; acc = 0.f; runc = 0.f;
        }
        acc += g_h[node * 128 + t];
        runc += 1.f;
    }
    if (cur >= 0) {
        atomicAdd(&g_pool[cur * 128 + t], acc);
        if (t == 0) atomicAdd(&g_gcnt[cur], runc);
    }
}

// ---------------- final projection ------------------------------------------
__global__ void __launch_bounds__(128) proj_kernel(const float* __restrict__ pW,
                                                   const float* __restrict__ pb,
                                                   float* __restrict__ out) {
    __shared__ float pr[128];
    int g = blockIdx.x, t = threadIdx.x;
    float c = fmaxf(g_gcnt[g], 1.f);
    pr[t] = g_pool[g * 128 + t] / c;
    __syncthreads();
    float acc = pb[t];
#pragma unroll 4
    for (int h = 0; h < 128; h++) acc = fmaf(pr[h], pW[t * 128 + h], acc);
    out[g * 128 + t] = acc;
}

// ---------------- cleanup: restore zero-invariant for next call -------------
__global__ void __launch_bounds__(256) cleanup_kernel() {
    int i = blockIdx.x * blockDim.x + threadIdx.x;
    if (i < NN) g_cnt[i] = 0;
    if (i < NG * HH) g_pool[i] = 0.f;
    if (i < NG) g_gcnt[i] = 0.f;
}

// ---------------- launch ------------------------------------------------------
extern "C" void kernel_launch(void* const* d_in, const int* in_sizes, int n_in,
                              void* d_out, int out_size) {
    const float* x       = (const float*)d_in[0];
    const int*   ei      = (const int*)  d_in[1];
    const float* ea      = (const float*)d_in[2];
    const int*   batch   = (const int*)  d_in[3];
    const float* node_W  = (const float*)d_in[4];
    const float* node_b  = (const float*)d_in[5];
    const float* edge_W  = (const float*)d_in[6];
    const float* edge_b  = (const float*)d_in[7];
    const float* lin1_W  = (const float*)d_in[8];
    const float* lin1_b  = (const float*)d_in[9];
    const float* bn_g    = (const float*)d_in[10];
    const float* bn_b    = (const float*)d_in[11];
    const float* bn_m    = (const float*)d_in[12];
    const float* bn_v    = (const float*)d_in[13];
    const float* lin2_W  = (const float*)d_in[14];
    const float* lin2_b  = (const float*)d_in[15];
    const float* proj_W  = (const float*)d_in[16];
    const float* proj_b  = (const float*)d_in[17];
    float* out = (float*)d_out;

    // #1 fused front (node_embed + hist + BN fold)
    fused_front<<<FUSED_GRID, 128>>>(x, node_W, node_b, ei,
                                     lin1_b, bn_g, bn_b, bn_m, bn_v);
    // #2 scan
    scan_kernel<<<1, 1024>>>();
    // #3 scatter
    scatter_kernel<<<(NE + 255) / 256, 256>>>(ei, ea);

    const int gemm_grid = (NN + 127) / 128;
    for (int li = 0; li < NL; li++) {
        // #4 (li==0) -> profiled
        aggregate_kernel<<<(NN * 32 + 255) / 256, 256>>>(edge_W, edge_b);
        gemm1_kernel<<<gemm_grid, 256>>>(lin1_W + li * HH * HH, li);
        gemm2_kernel<<<gemm_grid, 256>>>(lin2_W + li * HH * HH, lin2_b + li * HH);
    }

    pool_kernel<<<(NN + 127) / 128, 128>>>(batch);
    proj_kernel<<<NG, 128>>>(proj_W, proj_b, out);
    cleanup_kernel<<<(NN + 255) / 256, 256>>>();
}

// round 6
// speedup vs baseline: 1.0258x; 1.0027x over previous
#include <cuda_runtime.h>
#include <cuda_bf16.h>
#include <cstdint>

#define NN 50000
#define NE 800000
#define NG 64
#define NF 11
#define EF 14
#define HH 128
#define PP 128
#define NL 3
#define BN_EPS 1e-5f

#define NE_BLOCKS 1563          // node-embed blocks (32 nodes each)
#define HIST_BLOCKS 1563        // hist blocks (512 edges each)
#define FUSED_GRID (NE_BLOCKS + HIST_BLOCKS + 3)

// ---------------- scratch (__device__ globals; device-code references only) --
// Invariant: g_cnt, g_pool, g_gcnt are ZERO on entry to kernel_launch
// (zero-initialized at load; re-zeroed by cleanup_kernel at end of every call).
__device__ float g_h[NN * HH];
__device__ float g_z[NN * HH];
__device__ float g_t[NN * HH];
__device__ float g_eacsr[(size_t)NE * EF];
__device__ int   g_cnt[NN];
__device__ int   g_row[NN + 1];
__device__ int   g_cur[NN];
__device__ int   g_src[NE];
__device__ float g_scale[NL * HH];
__device__ float g_shift[NL * HH];
__device__ float g_pool[NG * HH];
__device__ float g_gcnt[NG];

// ---------------- launch #1: node_embed + edge histogram + BN fold ----------
__global__ void __launch_bounds__(128) fused_front(const float* __restrict__ x,
                                                   const float* __restrict__ nW,
                                                   const float* __restrict__ nb,
                                                   const int* __restrict__ ei,
                                                   const float* __restrict__ lin1_b,
                                                   const float* __restrict__ gamma,
                                                   const float* __restrict__ beta,
                                                   const float* __restrict__ mean,
                                                   const float* __restrict__ var) {
    int b = blockIdx.x;
    int t = threadIdx.x;
    if (b < NE_BLOCKS) {
        // node embedding: h = x @ node_W^T + node_b, 32 nodes per block
        __shared__ float xs[32 * NF];
        float w[NF];
#pragma unroll
        for (int k = 0; k < NF; k++) w[k] = nW[t * NF + k];
        float bias = nb[t];
        int base = b * 32;
        for (int i = t; i < 32 * NF; i += 128) {
            int node = base + i / NF;
            xs[i] = (node < NN) ? x[node * NF + i % NF] : 0.f;
        }
        __syncthreads();
        for (int j = 0; j < 32; j++) {
            int node = base + j;
            if (node >= NN) break;
            float acc = bias;
#pragma unroll
            for (int k = 0; k < NF; k++) acc = fmaf(xs[j * NF + k], w[k], acc);
            g_h[node * HH + t] = acc;
        }
    } else if (b < NE_BLOCKS + HIST_BLOCKS) {
        int base = (b - NE_BLOCKS) * 512;
#pragma unroll
        for (int r = 0; r < 4; r++) {
            int i = base + r * 128 + t;
            if (i < NE) atomicAdd(&g_cnt[ei[NE + i]], 1);
        }
    } else {
        int i = (b - NE_BLOCKS - HIST_BLOCKS) * 128 + t;
        if (i < NL * HH) {
            float sc = gamma[i] * rsqrtf(var[i] + BN_EPS);
            g_scale[i] = sc;
            g_shift[i] = (lin1_b[i] - mean[i]) * sc + beta[i];
        }
    }
}

// ---------------- launch #2: single-block scan ------------------------------
__global__ void __launch_bounds__(1024) scan_kernel() {
    __shared__ int partial[1024];
    const int CH = (NN + 1023) / 1024;   // 49
    int t = threadIdx.x;
    int beg = t * CH;
    int sum = 0;
    for (int i = 0; i < CH; i++) {
        int idx = beg + i;
        if (idx < NN) sum += g_cnt[idx];
    }
    partial[t] = sum;
    __syncthreads();
    for (int off = 1; off < 1024; off <<= 1) {
        int v = (t >= off) ? partial[t - off] : 0;
        __syncthreads();
        partial[t] += v;
        __syncthreads();
    }
    int run = (t > 0) ? partial[t - 1] : 0;
    for (int i = 0; i < CH; i++) {
        int idx = beg + i;
        if (idx < NN) {
            g_row[idx] = run;
            g_cur[idx] = run;
            run += g_cnt[idx];
        }
    }
    if (t == 1023) g_row[NN] = run;
}

// ---------------- launch #3: scatter (src + edge_attr permute) --------------
__global__ void __launch_bounds__(256) scatter_kernel(const int* __restrict__ ei,
                                                      const float* __restrict__ ea) {
    int i = blockIdx.x * blockDim.x + threadIdx.x;
    if (i < NE) {
        int d = ei[NE + i];
        int p = atomicAdd(&g_cur[d], 1);
        g_src[p] = ei[i];
        const float* s = ea + (size_t)i * EF;
        float* o = g_eacsr + (size_t)p * EF;
#pragma unroll
        for (int k = 0; k < EF; k++) o[k] = s[k];
    }
}

// ---------------- launch #4 (PROFILED): GINE aggregation --------------------
// z = h + sum_j relu(h[src] + e_ij); warp/node; e recomputed via shfl.
__global__ void __launch_bounds__(256) aggregate_kernel(const float* __restrict__ eW,
                                                        const float* __restrict__ eB) {
    int gid = blockIdx.x * blockDim.x + threadIdx.x;
    int node = gid >> 5;
    if (node >= NN) return;
    int lane = gid & 31;

    float w[4][EF];
    float eb[4];
#pragma unroll
    for (int c = 0; c < 4; c++) {
        eb[c] = eB[4 * lane + c];
#pragma unroll
        for (int k = 0; k < EF; k++) w[c][k] = eW[(4 * lane + c) * EF + k];
    }

    const float4* hp = (const float4*)g_h;
    float4 accA = make_float4(0.f, 0.f, 0.f, 0.f);
    float4 accB = make_float4(0.f, 0.f, 0.f, 0.f);
    int beg = g_row[node], end = g_row[node + 1];
    int i = beg;
    for (; i + 2 <= end; i += 2) {
        int s0 = __ldg(&g_src[i]);
        int s1 = __ldg(&g_src[i + 1]);
        float av0 = (lane < EF) ? __ldg(&g_eacsr[(size_t)i * EF + lane]) : 0.f;
        float av1 = (lane < EF) ? __ldg(&g_eacsr[(size_t)(i + 1) * EF + lane]) : 0.f;
        float4 h0 = hp[s0 * 32 + lane];
        float4 h1 = hp[s1 * 32 + lane];
        float a0 = eb[0], a1 = eb[1], a2 = eb[2], a3 = eb[3];
        float b0 = eb[0], b1 = eb[1], b2 = eb[2], b3 = eb[3];
#pragma unroll
        for (int k = 0; k < EF; k++) {
            float e0 = __shfl_sync(0xffffffffu, av0, k);
            float e1 = __shfl_sync(0xffffffffu, av1, k);
            a0 = fmaf(w[0][k], e0, a0); b0 = fmaf(w[0][k], e1, b0);
            a1 = fmaf(w[1][k], e0, a1); b1 = fmaf(w[1][k], e1, b1);
            a2 = fmaf(w[2][k], e0, a2); b2 = fmaf(w[2][k], e1, b2);
            a3 = fmaf(w[3][k], e0, a3); b3 = fmaf(w[3][k], e1, b3);
        }
        accA.x += fmaxf(h0.x + a0, 0.f);  accB.x += fmaxf(h1.x + b0, 0.f);
        accA.y += fmaxf(h0.y + a1, 0.f);  accB.y += fmaxf(h1.y + b1, 0.f);
        accA.z += fmaxf(h0.z + a2, 0.f);  accB.z += fmaxf(h1.z + b2, 0.f);
        accA.w += fmaxf(h0.w + a3, 0.f);  accB.w += fmaxf(h1.w + b3, 0.f);
    }
    if (i < end) {
        int s0 = __ldg(&g_src[i]);
        float av0 = (lane < EF) ? __ldg(&g_eacsr[(size_t)i * EF + lane]) : 0.f;
        float4 h0 = hp[s0 * 32 + lane];
        float a0 = eb[0], a1 = eb[1], a2 = eb[2], a3 = eb[3];
#pragma unroll
        for (int k = 0; k < EF; k++) {
            float e0 = __shfl_sync(0xffffffffu, av0, k);
            a0 = fmaf(w[0][k], e0, a0);
            a1 = fmaf(w[1][k], e0, a1);
            a2 = fmaf(w[2][k], e0, a2);
            a3 = fmaf(w[3][k], e0, a3);
        }
        accA.x += fmaxf(h0.x + a0, 0.f);
        accA.y += fmaxf(h0.y + a1, 0.f);
        accA.z += fmaxf(h0.z + a2, 0.f);
        accA.w += fmaxf(h0.w + a3, 0.f);
    }
    float4 hv = hp[node * 32 + lane];
    accA.x += accB.x + hv.x;
    accA.y += accB.y + hv.y;
    accA.z += accB.z + hv.z;
    accA.w += accB.w + hv.w;
    ((float4*)g_z)[node * 32 + lane] = accA;
}

// ---------------- SGEMM (R3 config): C[128 x 128], K=128, chunks of 32 ------
#define AL 132
#define WL 132

__device__ __forceinline__ void load_chunk(const float* __restrict__ A,
                                           const float* __restrict__ W,
                                           float* As, float* Ws,
                                           int rowbase, int kc, int t) {
    const float4* A4 = (const float4*)A;
    const float4* W4 = (const float4*)W;
    int kq4 = kc >> 2;
#pragma unroll
    for (int r = 0; r < 4; r++) {
        int idx = t + 256 * r;
        int m = idx >> 3;
        int kq = idx & 7;
        int row = rowbase + m;
        float4 v = make_float4(0.f, 0.f, 0.f, 0.f);
        if (row < NN) v = A4[row * 32 + kq4 + kq];
        As[(kq * 4 + 0) * AL + m] = v.x;
        As[(kq * 4 + 1) * AL + m] = v.y;
        As[(kq * 4 + 2) * AL + m] = v.z;
        As[(kq * 4 + 3) * AL + m] = v.w;
        float4 wv = W4[m * 32 + kq4 + kq];
        Ws[(kq * 4 + 0) * WL + m] = wv.x;
        Ws[(kq * 4 + 1) * WL + m] = wv.y;
        Ws[(kq * 4 + 2) * WL + m] = wv.z;
        Ws[(kq * 4 + 3) * WL + m] = wv.w;
    }
}

__device__ __forceinline__ void gemm_accum(const float* As, const float* Ws,
                                           int m0, int n0, float acc[8][8]) {
#pragma unroll
    for (int k = 0; k < 32; k++) {
        float4 a0 = *(const float4*)&As[k * AL + m0];
        float4 a1 = *(const float4*)&As[k * AL + m0 + 4];
        float4 b0 = *(const float4*)&Ws[k * WL + n0];
        float4 b1 = *(const float4*)&Ws[k * WL + n0 + 4];
        float a[8] = {a0.x, a0.y, a0.z, a0.w, a1.x, a1.y, a1.z, a1.w};
        float b[8] = {b0.x, b0.y, b0.z, b0.w, b1.x, b1.y, b1.z, b1.w};
#pragma unroll
        for (int j = 0; j < 8; j++)
#pragma unroll
            for (int i = 0; i < 8; i++) acc[j][i] = fmaf(a[j], b[i], acc[j][i]);
    }
}

// pass 1: g_t = relu(scale[li] * (g_z @ W1^T) + shift[li])
__global__ void __launch_bounds__(256) gemm1_kernel(const float* __restrict__ W1,
                                                    int li) {
    __shared__ float As[32 * AL];
    __shared__ float Ws[32 * WL];
    int t = threadIdx.x;
    int m0 = (t >> 4) * 8;
    int n0 = (t & 15) * 8;
    int rowbase = blockIdx.x * 128;

    float acc[8][8];
#pragma unroll
    for (int j = 0; j < 8; j++)
#pragma unroll
        for (int i = 0; i < 8; i++) acc[j][i] = 0.f;

    for (int kc = 0; kc < 128; kc += 32) {
        load_chunk(g_z, W1, As, Ws, rowbase, kc, t);
        __syncthreads();
        gemm_accum(As, Ws, m0, n0, acc);
        __syncthreads();
    }

    float sc[8], sh[8];
#pragma unroll
    for (int i = 0; i < 8; i++) {
        sc[i] = g_scale[li * HH + n0 + i];
        sh[i] = g_shift[li * HH + n0 + i];
    }
#pragma unroll
    for (int j = 0; j < 8; j++) {
        int row = rowbase + m0 + j;
        if (row < NN) {
            float o[8];
#pragma unroll
            for (int i = 0; i < 8; i++) o[i] = fmaxf(fmaf(acc[j][i], sc[i], sh[i]), 0.f);
            *(float4*)&g_t[row * 128 + n0]     = make_float4(o[0], o[1], o[2], o[3]);
            *(float4*)&g_t[row * 128 + n0 + 4] = make_float4(o[4], o[5], o[6], o[7]);
        }
    }
}

// pass 2: g_h = relu(g_t @ W2^T + b2) + g_h
__global__ void __launch_bounds__(256) gemm2_kernel(const float* __restrict__ W2,
                                                    const float* __restrict__ b2) {
    __shared__ float As[32 * AL];
    __shared__ float Ws[32 * WL];
    int t = threadIdx.x;
    int m0 = (t >> 4) * 8;
    int n0 = (t & 15) * 8;
    int rowbase = blockIdx.x * 128;

    float acc[8][8];
#pragma unroll
    for (int j = 0; j < 8; j++)
#pragma unroll
        for (int i = 0; i < 8; i++) acc[j][i] = 0.f;

    for (int kc = 0; kc < 128; kc += 32) {
        load_chunk(g_t, W2, As, Ws, rowbase, kc, t);
        __syncthreads();
        gemm_accum(As, Ws, m0, n0, acc);
        __syncthreads();
    }

    float bias[8];
#pragma unroll
    for (int i = 0; i < 8; i++) bias[i] = b2[n0 + i];
#pragma unroll
    for (int j = 0; j < 8; j++) {
        int row = rowbase + m0 + j;
        if (row < NN) {
            float4 h0 = *(const float4*)&g_h[row * 128 + n0];
            float4 h1 = *(const float4*)&g_h[row * 128 + n0 + 4];
            float4 o0, o1;
            o0.x = fmaxf(acc[j][0] + bias[0], 0.f) + h0.x;
            o0.y = fmaxf(acc[j][1] + bias[1], 0.f) + h0.y;
            o0.z = fmaxf(acc[j][2] + bias[2], 0.f) + h0.z;
            o0.w = fmaxf(acc[j][3] + bias[3], 0.f) + h0.w;
            o1.x = fmaxf(acc[j][4] + bias[4], 0.f) + h1.x;
            o1.y = fmaxf(acc[j][5] + bias[5], 0.f) + h1.y;
            o1.z = fmaxf(acc[j][6] + bias[6], 0.f) + h1.z;
            o1.w = fmaxf(acc[j][7] + bias[7], 0.f) + h1.w;
            *(float4*)&g_h[row * 128 + n0]     = o0;
            *(float4*)&g_h[row * 128 + n0 + 4] = o1;
        }
    }
}

// ---------------- pooling ----------------------------------------------------
__global__ void __launch_bounds__(128) pool_kernel(const int* __restrict__ batch) {
    int t = threadIdx.x;
    int base = blockIdx.x * 128;
    float acc = 0.f, runc = 0.f;
    int cur = -1;
    for (int j = 0; j < 128; j++) {
        int node = base + j;
        if (node >= NN) break;
        int g = batch[node];
        if (g != cur) {
            if (cur >= 0) {
                atomicAdd(&g_pool[cur * 128 + t], acc);
                if (t == 0) atomicAdd(&g_gcnt[cur], runc);
            }
            cur = g; acc = 0.f; runc = 0.f;
        }
        acc += g_h[node * 128 + t];
        runc += 1.f;
    }
    if (cur >= 0) {
        atomicAdd(&g_pool[cur * 128 + t], acc);
        if (t == 0) atomicAdd(&g_gcnt[cur], runc);
    }
}

// ---------------- final projection ------------------------------------------
__global__ void __launch_bounds__(128) proj_kernel(const float* __restrict__ pW,
                                                   const float* __restrict__ pb,
                                                   float* __restrict__ out) {
    __shared__ float pr[128];
    int g = blockIdx.x, t = threadIdx.x;
    float c = fmaxf(g_gcnt[g], 1.f);
    pr[t] = g_pool[g * 128 + t] / c;
    __syncthreads();
    float acc = pb[t];
#pragma unroll 4
    for (int h = 0; h < 128; h++) acc = fmaf(pr[h], pW[t * 128 + h], acc);
    out[g * 128 + t] = acc;
}

// ---------------- cleanup: restore zero-invariant for next call -------------
__global__ void __launch_bounds__(256) cleanup_kernel() {
    int i = blockIdx.x * blockDim.x + threadIdx.x;
    if (i < NN) g_cnt[i] = 0;
    if (i < NG * HH) g_pool[i] = 0.f;
    if (i < NG) g_gcnt[i] = 0.f;
}

// ---------------- launch ------------------------------------------------------
extern "C" void kernel_launch(void* const* d_in, const int* in_sizes, int n_in,
                              void* d_out, int out_size) {
    const float* x       = (const float*)d_in[0];
    const int*   ei      = (const int*)  d_in[1];
    const float* ea      = (const float*)d_in[2];
    const int*   batch   = (const int*)  d_in[3];
    const float* node_W  = (const float*)d_in[4];
    const float* node_b  = (const float*)d_in[5];
    const float* edge_W  = (const float*)d_in[6];
    const float* edge_b  = (const float*)d_in[7];
    const float* lin1_W  = (const float*)d_in[8];
    const float* lin1_b  = (const float*)d_in[9];
    const float* bn_g    = (const float*)d_in[10];
    const float* bn_b    = (const float*)d_in[11];
    const float* bn_m    = (const float*)d_in[12];
    const float* bn_v    = (const float*)d_in[13];
    const float* lin2_W  = (const float*)d_in[14];
    const float* lin2_b  = (const float*)d_in[15];
    const float* proj_W  = (const float*)d_in[16];
    const float* proj_b  = (const float*)d_in[17];
    float* out = (float*)d_out;

    // #1 fused front (node_embed + hist + BN fold)
    fused_front<<<FUSED_GRID, 128>>>(x, node_W, node_b, ei,
                                     lin1_b, bn_g, bn_b, bn_m, bn_v);
    // #2 scan
    scan_kernel<<<1, 1024>>>();
    // #3 scatter
    scatter_kernel<<<(NE + 255) / 256, 256>>>(ei, ea);

    const int gemm_grid = (NN + 127) / 128;
    for (int li = 0; li < NL; li++) {
        // #4 (li==0) -> profiled
        aggregate_kernel<<<(NN * 32 + 255) / 256, 256>>>(edge_W, edge_b);
        gemm1_kernel<<<gemm_grid, 256>>>(lin1_W + li * HH * HH, li);
        gemm2_kernel<<<gemm_grid, 256>>>(lin2_W + li * HH * HH, lin2_b + li * HH);
    }

    pool_kernel<<<(NN + 127) / 128, 128>>>(batch);
    proj_kernel<<<NG, 128>>>(proj_W, proj_b, out);
    cleanup_kernel<<<(NN + 255) / 256, 256>>>();
}

// round 7
// speedup vs baseline: 1.7598x; 1.7156x over previous
#include <cuda_runtime.h>
#include <cuda_bf16.h>
#include <cstdint>

#define NN 50000
#define NE 800000
#define NG 64
#define NF 11
#define EF 14
#define HH 128
#define PP 128
#define NL 3
#define BN_EPS 1e-5f

#define NE_BLOCKS 1563          // node-embed blocks (32 nodes each)
#define HIST_BLOCKS 1563        // hist blocks (512 edges each)
#define FUSED_GRID (NE_BLOCKS + HIST_BLOCKS + 3)

// ---------------- scratch (__device__ globals; device-code references only) --
// Invariant: g_cnt, g_pool, g_gcnt are ZERO on entry (re-zeroed by cleanup).
__device__ float g_h[NN * HH];
__device__ float g_z[NN * HH];
__device__ float g_t[NN * HH];
__device__ float g_e[(size_t)NE * HH];   // edge embeddings, CSR order (410MB)
__device__ int   g_cnt[NN];
__device__ int   g_row[NN + 1];
__device__ int   g_cur[NN];
__device__ int   g_src[NE];
__device__ float g_scale[NL * HH];
__device__ float g_shift[NL * HH];
__device__ float g_pool[NG * HH];
__device__ float g_gcnt[NG];

// ---------------- launch #1: node_embed + edge histogram + BN fold ----------
__global__ void __launch_bounds__(128) fused_front(const float* __restrict__ x,
                                                   const float* __restrict__ nW,
                                                   const float* __restrict__ nb,
                                                   const int* __restrict__ ei,
                                                   const float* __restrict__ lin1_b,
                                                   const float* __restrict__ gamma,
                                                   const float* __restrict__ beta,
                                                   const float* __restrict__ mean,
                                                   const float* __restrict__ var) {
    int b = blockIdx.x;
    int t = threadIdx.x;
    if (b < NE_BLOCKS) {
        __shared__ float xs[32 * NF];
        float w[NF];
#pragma unroll
        for (int k = 0; k < NF; k++) w[k] = nW[t * NF + k];
        float bias = nb[t];
        int base = b * 32;
        for (int i = t; i < 32 * NF; i += 128) {
            int node = base + i / NF;
            xs[i] = (node < NN) ? x[node * NF + i % NF] : 0.f;
        }
        __syncthreads();
        for (int j = 0; j < 32; j++) {
            int node = base + j;
            if (node >= NN) break;
            float acc = bias;
#pragma unroll
            for (int k = 0; k < NF; k++) acc = fmaf(xs[j * NF + k], w[k], acc);
            g_h[node * HH + t] = acc;
        }
    } else if (b < NE_BLOCKS + HIST_BLOCKS) {
        int base = (b - NE_BLOCKS) * 512;
#pragma unroll
        for (int r = 0; r < 4; r++) {
            int i = base + r * 128 + t;
            if (i < NE) atomicAdd(&g_cnt[ei[NE + i]], 1);
        }
    } else {
        int i = (b - NE_BLOCKS - HIST_BLOCKS) * 128 + t;
        if (i < NL * HH) {
            float sc = gamma[i] * rsqrtf(var[i] + BN_EPS);
            g_scale[i] = sc;
            g_shift[i] = (lin1_b[i] - mean[i]) * sc + beta[i];
        }
    }
}

// ---------------- launch #2: single-block scan ------------------------------
__global__ void __launch_bounds__(1024) scan_kernel() {
    __shared__ int partial[1024];
    const int CH = (NN + 1023) / 1024;   // 49
    int t = threadIdx.x;
    int beg = t * CH;
    int sum = 0;
    for (int i = 0; i < CH; i++) {
        int idx = beg + i;
        if (idx < NN) sum += g_cnt[idx];
    }
    partial[t] = sum;
    __syncthreads();
    for (int off = 1; off < 1024; off <<= 1) {
        int v = (t >= off) ? partial[t - off] : 0;
        __syncthreads();
        partial[t] += v;
        __syncthreads();
    }
    int run = (t > 0) ? partial[t - 1] : 0;
    for (int i = 0; i < CH; i++) {
        int idx = beg + i;
        if (idx < NN) {
            g_row[idx] = run;
            g_cur[idx] = run;
            run += g_cnt[idx];
        }
    }
    if (t == 1023) g_row[NN] = run;
}

// ---------------- launch #3: fused scatter + edge embedding -----------------
// 64 edges/block, 128 threads (one per output column).
// Threads 0..63 claim CSR slot + write g_src; then all threads compute the
// edge embedding and write the row directly at its CSR position in g_e.
__global__ void __launch_bounds__(128) edge_embed(const int* __restrict__ ei,
                                                  const float* __restrict__ ea,
                                                  const float* __restrict__ eW,
                                                  const float* __restrict__ eB) {
    __shared__ float es[64 * EF];
    __shared__ int pos[64];
    int t = threadIdx.x;
    int base = blockIdx.x * 64;

    if (t < 64) {
        int e = base + t;
        if (e < NE) {
            int d = ei[NE + e];
            int p = atomicAdd(&g_cur[d], 1);
            pos[t] = p;
            g_src[p] = ei[e];
        }
    }
    float w[EF];
#pragma unroll
    for (int k = 0; k < EF; k++) w[k] = eW[t * EF + k];
    float bias = eB[t];
    for (int i = t; i < 64 * EF; i += 128) {
        int e = base + i / EF;
        es[i] = (e < NE) ? ea[(size_t)e * EF + i % EF] : 0.f;
    }
    __syncthreads();
    int lim = NE - base; if (lim > 64) lim = 64;
    for (int j = 0; j < lim; j++) {
        float acc = bias;
#pragma unroll
        for (int k = 0; k < EF; k++) acc = fmaf(es[j * EF + k], w[k], acc);
        g_e[(size_t)pos[j] * HH + t] = acc;
    }
}

// ---------------- launch #4 (PROFILED): streaming GINE aggregation ----------
// z = h + sum_j relu(h[src] + e); warp/node; e read sequentially (CSR order).
__global__ void __launch_bounds__(256) aggregate_kernel() {
    int gid = blockIdx.x * blockDim.x + threadIdx.x;
    int node = gid >> 5;
    if (node >= NN) return;
    int lane = gid & 31;
    const float4* hp = (const float4*)g_h;
    const float4* ep = (const float4*)g_e;
    float4 accA = make_float4(0.f, 0.f, 0.f, 0.f);
    float4 accB = make_float4(0.f, 0.f, 0.f, 0.f);
    int beg = g_row[node], end = g_row[node + 1];
    int i = beg;
    for (; i + 2 <= end; i += 2) {
        int s0 = __ldg(&g_src[i]);
        int s1 = __ldg(&g_src[i + 1]);
        float4 e0 = ep[(size_t)i * 32 + lane];
        float4 e1 = ep[(size_t)(i + 1) * 32 + lane];
        float4 h0 = hp[s0 * 32 + lane];
        float4 h1 = hp[s1 * 32 + lane];
        accA.x += fmaxf(h0.x + e0.x, 0.f);  accB.x += fmaxf(h1.x + e1.x, 0.f);
        accA.y += fmaxf(h0.y + e0.y, 0.f);  accB.y += fmaxf(h1.y + e1.y, 0.f);
        accA.z += fmaxf(h0.z + e0.z, 0.f);  accB.z += fmaxf(h1.z + e1.z, 0.f);
        accA.w += fmaxf(h0.w + e0.w, 0.f);  accB.w += fmaxf(h1.w + e1.w, 0.f);
    }
    if (i < end) {
        int s0 = __ldg(&g_src[i]);
        float4 e0 = ep[(size_t)i * 32 + lane];
        float4 h0 = hp[s0 * 32 + lane];
        accA.x += fmaxf(h0.x + e0.x, 0.f);
        accA.y += fmaxf(h0.y + e0.y, 0.f);
        accA.z += fmaxf(h0.z + e0.z, 0.f);
        accA.w += fmaxf(h0.w + e0.w, 0.f);
    }
    float4 hv = hp[node * 32 + lane];
    accA.x += accB.x + hv.x;
    accA.y += accB.y + hv.y;
    accA.z += accB.z + hv.z;
    accA.w += accB.w + hv.w;
    ((float4*)g_z)[node * 32 + lane] = accA;
}

// ---------------- SGEMM (R3 config): C[128 x 128], K=128, chunks of 32 ------
#define AL 132
#define WL 132

__device__ __forceinline__ void load_chunk(const float* __restrict__ A,
                                           const float* __restrict__ W,
                                           float* As, float* Ws,
                                           int rowbase, int kc, int t) {
    const float4* A4 = (const float4*)A;
    const float4* W4 = (const float4*)W;
    int kq4 = kc >> 2;
#pragma unroll
    for (int r = 0; r < 4; r++) {
        int idx = t + 256 * r;
        int m = idx >> 3;
        int kq = idx & 7;
        int row = rowbase + m;
        float4 v = make_float4(0.f, 0.f, 0.f, 0.f);
        if (row < NN) v = A4[row * 32 + kq4 + kq];
        As[(kq * 4 + 0) * AL + m] = v.x;
        As[(kq * 4 + 1) * AL + m] = v.y;
        As[(kq * 4 + 2) * AL + m] = v.z;
        As[(kq * 4 + 3) * AL + m] = v.w;
        float4 wv = W4[m * 32 + kq4 + kq];
        Ws[(kq * 4 + 0) * WL + m] = wv.x;
        Ws[(kq * 4 + 1) * WL + m] = wv.y;
        Ws[(kq * 4 + 2) * WL + m] = wv.z;
        Ws[(kq * 4 + 3) * WL + m] = wv.w;
    }
}

__device__ __forceinline__ void gemm_accum(const float* As, const float* Ws,
                                           int m0, int n0, float acc[8][8]) {
#pragma unroll
    for (int k = 0; k < 32; k++) {
        float4 a0 = *(const float4*)&As[k * AL + m0];
        float4 a1 = *(const float4*)&As[k * AL + m0 + 4];
        float4 b0 = *(const float4*)&Ws[k * WL + n0];
        float4 b1 = *(const float4*)&Ws[k * WL + n0 + 4];
        float a[8] = {a0.x, a0.y, a0.z, a0.w, a1.x, a1.y, a1.z, a1.w};
        float b[8] = {b0.x, b0.y, b0.z, b0.w, b1.x, b1.y, b1.z, b1.w};
#pragma unroll
        for (int j = 0; j < 8; j++)
#pragma unroll
            for (int i = 0; i < 8; i++) acc[j][i] = fmaf(a[j], b[i], acc[j][i]);
    }
}

// pass 1: g_t = relu(scale[li] * (g_z @ W1^T) + shift[li])
__global__ void __launch_bounds__(256) gemm1_kernel(const float* __restrict__ W1,
                                                    int li) {
    __shared__ float As[32 * AL];
    __shared__ float Ws[32 * WL];
    int t = threadIdx.x;
    int m0 = (t >> 4) * 8;
    int n0 = (t & 15) * 8;
    int rowbase = blockIdx.x * 128;

    float acc[8][8];
#pragma unroll
    for (int j = 0; j < 8; j++)
#pragma unroll
        for (int i = 0; i < 8; i++) acc[j][i] = 0.f;

    for (int kc = 0; kc < 128; kc += 32) {
        load_chunk(g_z, W1, As, Ws, rowbase, kc, t);
        __syncthreads();
        gemm_accum(As, Ws, m0, n0, acc);
        __syncthreads();
    }

    float sc[8], sh[8];
#pragma unroll
    for (int i = 0; i < 8; i++) {
        sc[i] = g_scale[li * HH + n0 + i];
        sh[i] = g_shift[li * HH + n0 + i];
    }
#pragma unroll
    for (int j = 0; j < 8; j++) {
        int row = rowbase + m0 + j;
        if (row < NN) {
            float o[8];
#pragma unroll
            for (int i = 0; i < 8; i++) o[i] = fmaxf(fmaf(acc[j][i], sc[i], sh[i]), 0.f);
            *(float4*)&g_t[row * 128 + n0]     = make_float4(o[0], o[1], o[2], o[3]);
            *(float4*)&g_t[row * 128 + n0 + 4] = make_float4(o[4], o[5], o[6], o[7]);
        }
    }
}

// pass 2: g_h = relu(g_t @ W2^T + b2) + g_h
__global__ void __launch_bounds__(256) gemm2_kernel(const float* __restrict__ W2,
                                                    const float* __restrict__ b2) {
    __shared__ float As[32 * AL];
    __shared__ float Ws[32 * WL];
    int t = threadIdx.x;
    int m0 = (t >> 4) * 8;
    int n0 = (t & 15) * 8;
    int rowbase = blockIdx.x * 128;

    float acc[8][8];
#pragma unroll
    for (int j = 0; j < 8; j++)
#pragma unroll
        for (int i = 0; i < 8; i++) acc[j][i] = 0.f;

    for (int kc = 0; kc < 128; kc += 32) {
        load_chunk(g_t, W2, As, Ws, rowbase, kc, t);
        __syncthreads();
        gemm_accum(As, Ws, m0, n0, acc);
        __syncthreads();
    }

    float bias[8];
#pragma unroll
    for (int i = 0; i < 8; i++) bias[i] = b2[n0 + i];
#pragma unroll
    for (int j = 0; j < 8; j++) {
        int row = rowbase + m0 + j;
        if (row < NN) {
            float4 h0 = *(const float4*)&g_h[row * 128 + n0];
            float4 h1 = *(const float4*)&g_h[row * 128 + n0 + 4];
            float4 o0, o1;
            o0.x = fmaxf(acc[j][0] + bias[0], 0.f) + h0.x;
            o0.y = fmaxf(acc[j][1] + bias[1], 0.f) + h0.y;
            o0.z = fmaxf(acc[j][2] + bias[2], 0.f) + h0.z;
            o0.w = fmaxf(acc[j][3] + bias[3], 0.f) + h0.w;
            o1.x = fmaxf(acc[j][4] + bias[4], 0.f) + h1.x;
            o1.y = fmaxf(acc[j][5] + bias[5], 0.f) + h1.y;
            o1.z = fmaxf(acc[j][6] + bias[6], 0.f) + h1.z;
            o1.w = fmaxf(acc[j][7] + bias[7], 0.f) + h1.w;
            *(float4*)&g_h[row * 128 + n0]     = o0;
            *(float4*)&g_h[row * 128 + n0 + 4] = o1;
        }
    }
}

// ---------------- pooling ----------------------------------------------------
__global__ void __launch_bounds__(128) pool_kernel(const int* __restrict__ batch) {
    int t = threadIdx.x;
    int base = blockIdx.x * 128;
    float acc = 0.f, runc = 0.f;
    int cur = -1;
    for (int j = 0; j < 128; j++) {
        int node = base + j;
        if (node >= NN) break;
        int g = batch[node];
        if (g != cur) {
            if (cur >= 0) {
                atomicAdd(&g_pool[cur * 128 + t], acc);
                if (t == 0) atomicAdd(&g_gcnt[cur], runc);
            }
            cur = g; acc = 0.f; runc = 0.f;
        }
        acc += g_h[node * 128 + t];
        runc += 1.f;
    }
    if (cur >= 0) {
        atomicAdd(&g_pool[cur * 128 + t], acc);
        if (t == 0) atomicAdd(&g_gcnt[cur], runc);
    }
}

// ---------------- final projection ------------------------------------------
__global__ void __launch_bounds__(128) proj_kernel(const float* __restrict__ pW,
                                                   const float* __restrict__ pb,
                                                   float* __restrict__ out) {
    __shared__ float pr[128];
    int g = blockIdx.x, t = threadIdx.x;
    float c = fmaxf(g_gcnt[g], 1.f);
    pr[t] = g_pool[g * 128 + t] / c;
    __syncthreads();
    float acc = pb[t];
#pragma unroll 4
    for (int h = 0; h < 128; h++) acc = fmaf(pr[h], pW[t * 128 + h], acc);
    out[g * 128 + t] = acc;
}

// ---------------- cleanup: restore zero-invariant for next call -------------
__global__ void __launch_bounds__(256) cleanup_kernel() {
    int i = blockIdx.x * blockDim.x + threadIdx.x;
    if (i < NN) g_cnt[i] = 0;
    if (i < NG * HH) g_pool[i] = 0.f;
    if (i < NG) g_gcnt[i] = 0.f;
}

// ---------------- launch ------------------------------------------------------
extern "C" void kernel_launch(void* const* d_in, const int* in_sizes, int n_in,
                              void* d_out, int out_size) {
    const float* x       = (const float*)d_in[0];
    const int*   ei      = (const int*)  d_in[1];
    const float* ea      = (const float*)d_in[2];
    const int*   batch   = (const int*)  d_in[3];
    const float* node_W  = (const float*)d_in[4];
    const float* node_b  = (const float*)d_in[5];
    const float* edge_W  = (const float*)d_in[6];
    const float* edge_b  = (const float*)d_in[7];
    const float* lin1_W  = (const float*)d_in[8];
    const float* lin1_b  = (const float*)d_in[9];
    const float* bn_g    = (const float*)d_in[10];
    const float* bn_b    = (const float*)d_in[11];
    const float* bn_m    = (const float*)d_in[12];
    const float* bn_v    = (const float*)d_in[13];
    const float* lin2_W  = (const float*)d_in[14];
    const float* lin2_b  = (const float*)d_in[15];
    const float* proj_W  = (const float*)d_in[16];
    const float* proj_b  = (const float*)d_in[17];
    float* out = (float*)d_out;

    // #1 fused front (node_embed + hist + BN fold)
    fused_front<<<FUSED_GRID, 128>>>(x, node_W, node_b, ei,
                                     lin1_b, bn_g, bn_b, bn_m, bn_v);
    // #2 scan
    scan_kernel<<<1, 1024>>>();
    // #3 fused scatter + edge embedding (writes g_e in CSR order)
    edge_embed<<<(NE + 63) / 64, 128>>>(ei, ea, edge_W, edge_b);

    const int gemm_grid = (NN + 127) / 128;
    for (int li = 0; li < NL; li++) {
        // #4 (li==0) -> profiled: verifies streaming-aggregate prediction
        aggregate_kernel<<<(NN * 32 + 255) / 256, 256>>>();
        gemm1_kernel<<<gemm_grid, 256>>>(lin1_W + li * HH * HH, li);
        gemm2_kernel<<<gemm_grid, 256>>>(lin2_W + li * HH * HH, lin2_b + li * HH);
    }

    pool_kernel<<<(NN + 127) / 128, 128>>>(batch);
    proj_kernel<<<NG, 128>>>(proj_W, proj_b, out);
    cleanup_kernel<<<(NN + 255) / 256, 256>>>();
}